// round 6
// baseline (speedup 1.0000x reference)
#include <cuda_runtime.h>

#define FDIM 128
#define DEG 16
#define MAXN 65536
#define EPS 1e-12f
#define WPB 4          // warps per block (agnn)

// Scratch: per-node inverse L2 norm (allocation-free rule -> __device__ global)
__device__ float g_rn[MAXN];

__device__ __forceinline__ float warp_sum(float p) {
#pragma unroll
    for (int o = 16; o; o >>= 1) p += __shfl_xor_sync(0xffffffffu, p, o);
    return p;
}

// ---------------------------------------------------------------------------
// Kernel 1: per-node inverse norm. One warp per node, float4 per lane.
// ---------------------------------------------------------------------------
__global__ void norm_kernel(const float* __restrict__ x, int n) {
    int warp = (blockIdx.x * blockDim.x + threadIdx.x) >> 5;
    int lane = threadIdx.x & 31;
    if (warp >= n) return;
    const float4* xr = reinterpret_cast<const float4*>(x + (size_t)warp * FDIM);
    float4 v = xr[lane];
    float s = warp_sum(v.x * v.x + v.y * v.y + v.z * v.z + v.w * v.w);
    if (lane == 0) g_rn[warp] = rsqrtf(s + EPS);
}

// ---------------------------------------------------------------------------
// Kernel 2: AGNN, one warp per node.
//  - all 16 neighbor rows staged via cp.async (MLP=16, zero reg pressure)
//  - per-thread wait_group pipelining; each lane reads only its own 16B slice
//  - pair-fold shuffle reduction; -|beta| shift (no max pass); shared expf
// ---------------------------------------------------------------------------
__global__ __launch_bounds__(128, 7) void agnn_kernel(
    const float* __restrict__ x,
    const int*   __restrict__ row_ptr,
    const int*   __restrict__ col_id,
    const float* __restrict__ beta,
    float*       __restrict__ out,
    int n)
{
    __shared__ float4 buf[WPB][DEG][32];   // 32 KB

    int tid    = threadIdx.x;
    int wlocal = tid >> 5;
    int lane   = tid & 31;
    int warp   = blockIdx.x * WPB + wlocal;
    if (warp >= n) return;

    int   base = row_ptr[warp];
    float b    = beta[0];
    float babs = fabsf(b);
    bool  hi   = (lane & 16) != 0;

    // Neighbor indices (warp-uniform)
    int cols[DEG];
#pragma unroll
    for (int j = 0; j < DEG; j++) cols[j] = __ldg(&col_id[base + j]);

    // Stage all 16 neighbor rows: each lane copies its own 16B slice.
#pragma unroll
    for (int p = 0; p < DEG / 2; p++) {
        const float* sa = x + (size_t)cols[2 * p]     * FDIM + lane * 4;
        const float* sb = x + (size_t)cols[2 * p + 1] * FDIM + lane * 4;
        unsigned da = (unsigned)__cvta_generic_to_shared(&buf[wlocal][2 * p][lane]);
        unsigned db = (unsigned)__cvta_generic_to_shared(&buf[wlocal][2 * p + 1][lane]);
        asm volatile("cp.async.cg.shared.global [%0], [%1], 16;" :: "r"(da), "l"(sa));
        asm volatile("cp.async.cg.shared.global [%0], [%1], 16;" :: "r"(db), "l"(sb));
        asm volatile("cp.async.commit_group;");
    }

    // Prefetch neighbor inverse norms (uniform scalars) while gathers fly.
    float rnv[DEG];
#pragma unroll
    for (int j = 0; j < DEG; j++) rnv[j] = __ldg(&g_rn[cols[j]]);

    // Self row + folded query scale
    const float4* xi = reinterpret_cast<const float4*>(x + (size_t)warp * FDIM);
    float4 vi = xi[lane];
    float  kq = b * g_rn[warp];
    float4 vip = make_float4(vi.x * kq, vi.y * kq, vi.z * kq, vi.w * kq);

    float  s   = 0.0f;
    float4 acc = make_float4(0.f, 0.f, 0.f, 0.f);

#define PROC_PAIR(P, W)                                                        \
    do {                                                                       \
        asm volatile("cp.async.wait_group %0;" :: "n"(W));                     \
        float4 va = buf[wlocal][2 * (P)][lane];                                \
        float4 vb = buf[wlocal][2 * (P) + 1][lane];                            \
        float pa = vip.x * va.x + vip.y * va.y + vip.z * va.z + vip.w * va.w;  \
        float pb = vip.x * vb.x + vip.y * vb.y + vip.z * vb.z + vip.w * vb.w;  \
        float keep  = hi ? pb : pa;                                            \
        float other = hi ? pa : pb;                                            \
        float q = keep + __shfl_xor_sync(0xffffffffu, other, 16);              \
        q += __shfl_xor_sync(0xffffffffu, q, 8);                               \
        q += __shfl_xor_sync(0xffffffffu, q, 4);                               \
        q += __shfl_xor_sync(0xffffffffu, q, 2);                               \
        q += __shfl_xor_sync(0xffffffffu, q, 1);                               \
        float rnsel = hi ? rnv[2 * (P) + 1] : rnv[2 * (P)];                    \
        float e = fmaf(q, rnsel, -babs);                                       \
        float w = __expf(e);                                                   \
        float wa = __shfl_sync(0xffffffffu, w, 0);                             \
        float wb = __shfl_sync(0xffffffffu, w, 16);                            \
        s += wa + wb;                                                          \
        acc.x += wa * va.x + wb * vb.x;                                        \
        acc.y += wa * va.y + wb * vb.y;                                        \
        acc.z += wa * va.z + wb * vb.z;                                        \
        acc.w += wa * va.w + wb * vb.w;                                        \
    } while (0)

    PROC_PAIR(0, 7);
    PROC_PAIR(1, 6);
    PROC_PAIR(2, 5);
    PROC_PAIR(3, 4);
    PROC_PAIR(4, 3);
    PROC_PAIR(5, 2);
    PROC_PAIR(6, 1);
    PROC_PAIR(7, 0);
#undef PROC_PAIR

    float inv = 1.0f / s;
    float4 o = make_float4(acc.x * inv, acc.y * inv, acc.z * inv, acc.w * inv);
    reinterpret_cast<float4*>(out + (size_t)warp * FDIM)[lane] = o;
}

// ---------------------------------------------------------------------------
// Launch
// ---------------------------------------------------------------------------
extern "C" void kernel_launch(void* const* d_in, const int* in_sizes, int n_in,
                              void* d_out, int out_size) {
    const float* x       = (const float*)d_in[0];
    // d_in[1] = row_id (COO) — not needed with CSR + fixed degree
    const int*   row_ptr = (const int*)d_in[2];
    const int*   col_id  = (const int*)d_in[3];
    const float* beta    = (const float*)d_in[4];
    float*       out     = (float*)d_out;

    int n = in_sizes[2] - 1;   // row_ptr has N+1 entries
    if (n > MAXN) n = MAXN;    // defensive: scratch bound (no-op for this shape)

    int nthreads = 256;
    int nblocks  = (n * 32 + nthreads - 1) / nthreads;
    norm_kernel<<<nblocks, nthreads>>>(x, n);

    int ablocks = (n + WPB - 1) / WPB;
    agnn_kernel<<<ablocks, 128>>>(x, row_ptr, col_id, beta, out, n);
}

// round 7
// speedup vs baseline: 1.1646x; 1.1646x over previous
#include <cuda_runtime.h>

#define FDIM 128
#define DEG 16
#define MAXN 65536
#define EPS 1e-12f

// Scratch: per-node inverse L2 norm (allocation-free rule -> __device__ global)
__device__ float g_rn[MAXN];

__device__ __forceinline__ float warp_sum(float p) {
#pragma unroll
    for (int o = 16; o; o >>= 1) p += __shfl_xor_sync(0xffffffffu, p, o);
    return p;
}

// ---------------------------------------------------------------------------
// Kernel 1: per-node inverse norm. One warp per node, float4 per lane.
// ---------------------------------------------------------------------------
__global__ void norm_kernel(const float* __restrict__ x, int n) {
    int warp = (blockIdx.x * blockDim.x + threadIdx.x) >> 5;
    int lane = threadIdx.x & 31;
    if (warp >= n) return;
    const float4* xr = reinterpret_cast<const float4*>(x + (size_t)warp * FDIM);
    float4 v = xr[lane];
    float s = warp_sum(v.x * v.x + v.y * v.y + v.z * v.z + v.w * v.w);
    if (lane == 0) g_rn[warp] = rsqrtf(s + EPS);
}

// ---------------------------------------------------------------------------
// Kernel 2: AGNN, one warp per node, neighbors processed in QUADS:
//  - 4 dot-product partials folded into warp quarters (offset16, offset8),
//    then 3 shared butterfly steps -> 7 shfl + 4 bcast per 4 neighbors
//  - scores bounded by |beta| -> shift by -|beta|, no max pass
//  - one __expf per lane covers 4 neighbors
//  - transient per-quad index/norm loads keep regs <= 48 (occ cap 62.5%)
// ---------------------------------------------------------------------------
__global__ __launch_bounds__(256, 5) void agnn_kernel(
    const float* __restrict__ x,
    const int*   __restrict__ col_id,
    const float* __restrict__ beta,
    float*       __restrict__ out,
    int n)
{
    int warp = (blockIdx.x * blockDim.x + threadIdx.x) >> 5;
    int lane = threadIdx.x & 31;
    if (warp >= n) return;

    float b    = beta[0];
    float babs = fabsf(b);
    bool  b4   = (lane & 16) != 0;
    bool  b3   = (lane & 8)  != 0;

    const float4* xi = reinterpret_cast<const float4*>(x + (size_t)warp * FDIM);
    float4 vi = xi[lane];
    float  kq = b * g_rn[warp];
    float4 vip = make_float4(vi.x * kq, vi.y * kq, vi.z * kq, vi.w * kq);

    // Fixed degree: this node's 16 indices start at warp*DEG (64B aligned).
    const int4* cidx = reinterpret_cast<const int4*>(col_id + (size_t)warp * DEG);

    float  s   = 0.0f;
    float4 acc = make_float4(0.f, 0.f, 0.f, 0.f);

#pragma unroll
    for (int qd = 0; qd < DEG / 4; qd++) {
        int4 c = __ldg(&cidx[qd]);
        const float4* x0 = reinterpret_cast<const float4*>(x + (size_t)c.x * FDIM);
        const float4* x1 = reinterpret_cast<const float4*>(x + (size_t)c.y * FDIM);
        const float4* x2 = reinterpret_cast<const float4*>(x + (size_t)c.z * FDIM);
        const float4* x3 = reinterpret_cast<const float4*>(x + (size_t)c.w * FDIM);
        float4 v0 = x0[lane];
        float4 v1 = x1[lane];
        float4 v2 = x2[lane];
        float4 v3 = x3[lane];
        float rn0 = __ldg(&g_rn[c.x]);
        float rn1 = __ldg(&g_rn[c.y]);
        float rn2 = __ldg(&g_rn[c.z]);
        float rn3 = __ldg(&g_rn[c.w]);

        float p0 = vip.x * v0.x + vip.y * v0.y + vip.z * v0.z + vip.w * v0.w;
        float p1 = vip.x * v1.x + vip.y * v1.y + vip.z * v1.z + vip.w * v1.w;
        float p2 = vip.x * v2.x + vip.y * v2.y + vip.z * v2.z + vip.w * v2.w;
        float p3 = vip.x * v3.x + vip.y * v3.y + vip.z * v3.z + vip.w * v3.w;

        // Fold at offset 16: low half keeps p0/p2 partials, high half p1/p3.
        float u = (b4 ? p1 : p0) + __shfl_xor_sync(0xffffffffu, b4 ? p0 : p1, 16);
        float v = (b4 ? p3 : p2) + __shfl_xor_sync(0xffffffffu, b4 ? p2 : p3, 16);
        // Fold at offset 8: quarters -> (b4,b3): (0,0)=n0 (0,1)=n2 (1,0)=n1 (1,1)=n3
        float q = (b3 ? v : u) + __shfl_xor_sync(0xffffffffu, b3 ? u : v, 8);
        // Shared butterfly within 8-lane groups.
        q += __shfl_xor_sync(0xffffffffu, q, 4);
        q += __shfl_xor_sync(0xffffffffu, q, 2);
        q += __shfl_xor_sync(0xffffffffu, q, 1);

        float rnsel = b4 ? (b3 ? rn3 : rn1) : (b3 ? rn2 : rn0);
        float e = fmaf(q, rnsel, -babs);   // beta*cos - |beta| <= 0
        float w = __expf(e);

        float w0 = __shfl_sync(0xffffffffu, w, 0);
        float w2 = __shfl_sync(0xffffffffu, w, 8);
        float w1 = __shfl_sync(0xffffffffu, w, 16);
        float w3 = __shfl_sync(0xffffffffu, w, 24);

        s += (w0 + w1) + (w2 + w3);
        acc.x = fmaf(w0, v0.x, fmaf(w1, v1.x, fmaf(w2, v2.x, fmaf(w3, v3.x, acc.x))));
        acc.y = fmaf(w0, v0.y, fmaf(w1, v1.y, fmaf(w2, v2.y, fmaf(w3, v3.y, acc.y))));
        acc.z = fmaf(w0, v0.z, fmaf(w1, v1.z, fmaf(w2, v2.z, fmaf(w3, v3.z, acc.z))));
        acc.w = fmaf(w0, v0.w, fmaf(w1, v1.w, fmaf(w2, v2.w, fmaf(w3, v3.w, acc.w))));
    }

    float inv = 1.0f / s;
    float4 o = make_float4(acc.x * inv, acc.y * inv, acc.z * inv, acc.w * inv);
    reinterpret_cast<float4*>(out + (size_t)warp * FDIM)[lane] = o;
}

// ---------------------------------------------------------------------------
// Launch
// ---------------------------------------------------------------------------
extern "C" void kernel_launch(void* const* d_in, const int* in_sizes, int n_in,
                              void* d_out, int out_size) {
    const float* x       = (const float*)d_in[0];
    // d_in[1] = row_id (COO), d_in[2] = row_ptr — fixed degree, base = node*16
    const int*   col_id  = (const int*)d_in[3];
    const float* beta    = (const float*)d_in[4];
    float*       out     = (float*)d_out;

    int n = in_sizes[2] - 1;   // row_ptr has N+1 entries
    if (n > MAXN) n = MAXN;    // defensive: scratch bound (no-op for this shape)

    int threads = 256;
    int blocks  = (n * 32 + threads - 1) / threads;

    norm_kernel<<<blocks, threads>>>(x, n);
    agnn_kernel<<<blocks, threads>>>(x, col_id, beta, out, n);
}

// round 8
// speedup vs baseline: 1.2209x; 1.0484x over previous
#include <cuda_runtime.h>

#define FDIM 128
#define DEG 16
#define MAXN 65536
#define EPS 1e-12f

// Scratch: per-node inverse L2 norm (allocation-free rule -> __device__ global)
__device__ float g_rn[MAXN];

__device__ __forceinline__ float warp_sum(float p) {
#pragma unroll
    for (int o = 16; o; o >>= 1) p += __shfl_xor_sync(0xffffffffu, p, o);
    return p;
}

// ---------------------------------------------------------------------------
// Kernel 1: per-node inverse norm. One warp per node, float4 per lane.
// ---------------------------------------------------------------------------
__global__ void norm_kernel(const float* __restrict__ x, int n) {
    int warp = (blockIdx.x * blockDim.x + threadIdx.x) >> 5;
    int lane = threadIdx.x & 31;
    if (warp >= n) return;
    const float4* xr = reinterpret_cast<const float4*>(x + (size_t)warp * FDIM);
    float4 v = xr[lane];
    float s = warp_sum(v.x * v.x + v.y * v.y + v.z * v.z + v.w * v.w);
    if (lane == 0) g_rn[warp] = rsqrtf(s + EPS);
}

// ---------------------------------------------------------------------------
// Kernel 2: AGNN, one warp per node, neighbors in QUADS.
//  - quad-fold shuffle reduction (7 shfl + 4 bcast per 4 neighbors)
//  - -|beta| shift instead of max pass; one __expf per lane per quad
//  - ONE g_rn load per lane (group-selected id, L2 broadcast) -> fewer regs
//  - 32-bit gather offsets; reg budget 42 (launch_bounds 256,6; occ cap 75%)
// ---------------------------------------------------------------------------
__global__ __launch_bounds__(256, 6) void agnn_kernel(
    const float* __restrict__ x,
    const int*   __restrict__ col_id,
    const float* __restrict__ beta,
    float*       __restrict__ out,
    int n)
{
    int warp = (blockIdx.x * blockDim.x + threadIdx.x) >> 5;
    int lane = threadIdx.x & 31;
    if (warp >= n) return;

    float b    = beta[0];
    float babs = fabsf(b);
    bool  b4   = (lane & 16) != 0;
    bool  b3   = (lane & 8)  != 0;

    const float4* xv = reinterpret_cast<const float4*>(x);   // row = 32 float4
    float4 vi = xv[((unsigned)warp << 5) + lane];
    float  kq = b * g_rn[warp];
    float4 vip = make_float4(vi.x * kq, vi.y * kq, vi.z * kq, vi.w * kq);

    // Fixed degree: this node's 16 indices start at warp*DEG (64B aligned).
    const int4* cidx = reinterpret_cast<const int4*>(col_id) + ((unsigned)warp << 2);

    float  s   = 0.0f;
    float4 acc = make_float4(0.f, 0.f, 0.f, 0.f);

#pragma unroll
    for (int qd = 0; qd < DEG / 4; qd++) {
        int4 c = __ldg(&cidx[qd]);
        float4 v0 = xv[((unsigned)c.x << 5) + lane];
        float4 v1 = xv[((unsigned)c.y << 5) + lane];
        float4 v2 = xv[((unsigned)c.z << 5) + lane];
        float4 v3 = xv[((unsigned)c.w << 5) + lane];

        // Group-owned neighbor id: (b4,b3) -> (0,0)=c.x (0,1)=c.z (1,0)=c.y (1,1)=c.w
        int   csel  = b4 ? (b3 ? c.w : c.y) : (b3 ? c.z : c.x);
        float rnsel = __ldg(&g_rn[csel]);   // 8-lane group shares one address

        float p0 = vip.x * v0.x + vip.y * v0.y + vip.z * v0.z + vip.w * v0.w;
        float p1 = vip.x * v1.x + vip.y * v1.y + vip.z * v1.z + vip.w * v1.w;
        float p2 = vip.x * v2.x + vip.y * v2.y + vip.z * v2.z + vip.w * v2.w;
        float p3 = vip.x * v3.x + vip.y * v3.y + vip.z * v3.z + vip.w * v3.w;

        // Fold at offset 16: low half keeps p0/p2 partials, high half p1/p3.
        float u = (b4 ? p1 : p0) + __shfl_xor_sync(0xffffffffu, b4 ? p0 : p1, 16);
        float v = (b4 ? p3 : p2) + __shfl_xor_sync(0xffffffffu, b4 ? p2 : p3, 16);
        // Fold at offset 8 -> each 8-lane group owns one neighbor's partial.
        float q = (b3 ? v : u) + __shfl_xor_sync(0xffffffffu, b3 ? u : v, 8);
        // Shared butterfly within 8-lane groups.
        q += __shfl_xor_sync(0xffffffffu, q, 4);
        q += __shfl_xor_sync(0xffffffffu, q, 2);
        q += __shfl_xor_sync(0xffffffffu, q, 1);

        float e = fmaf(q, rnsel, -babs);   // beta*cos - |beta| <= 0
        float w = __expf(e);

        float w0 = __shfl_sync(0xffffffffu, w, 0);
        float w2 = __shfl_sync(0xffffffffu, w, 8);
        float w1 = __shfl_sync(0xffffffffu, w, 16);
        float w3 = __shfl_sync(0xffffffffu, w, 24);

        s += (w0 + w1) + (w2 + w3);
        acc.x = fmaf(w0, v0.x, fmaf(w1, v1.x, fmaf(w2, v2.x, fmaf(w3, v3.x, acc.x))));
        acc.y = fmaf(w0, v0.y, fmaf(w1, v1.y, fmaf(w2, v2.y, fmaf(w3, v3.y, acc.y))));
        acc.z = fmaf(w0, v0.z, fmaf(w1, v1.z, fmaf(w2, v2.z, fmaf(w3, v3.z, acc.z))));
        acc.w = fmaf(w0, v0.w, fmaf(w1, v1.w, fmaf(w2, v2.w, fmaf(w3, v3.w, acc.w))));
    }

    float inv = 1.0f / s;
    float4 o = make_float4(acc.x * inv, acc.y * inv, acc.z * inv, acc.w * inv);
    reinterpret_cast<float4*>(out)[((unsigned)warp << 5) + lane] = o;
}

// ---------------------------------------------------------------------------
// Launch
// ---------------------------------------------------------------------------
extern "C" void kernel_launch(void* const* d_in, const int* in_sizes, int n_in,
                              void* d_out, int out_size) {
    const float* x       = (const float*)d_in[0];
    // d_in[1] = row_id (COO), d_in[2] = row_ptr — fixed degree, base = node*16
    const int*   col_id  = (const int*)d_in[3];
    const float* beta    = (const float*)d_in[4];
    float*       out     = (float*)d_out;

    int n = in_sizes[2] - 1;   // row_ptr has N+1 entries
    if (n > MAXN) n = MAXN;    // defensive: scratch bound (no-op for this shape)

    int threads = 256;
    int blocks  = (n * 32 + threads - 1) / threads;

    norm_kernel<<<blocks, threads>>>(x, n);
    agnn_kernel<<<blocks, threads>>>(x, col_id, beta, out, n);
}